// round 9
// baseline (speedup 1.0000x reference)
#include <cuda_runtime.h>
#include <cstdint>

// B=8, C=4, H=W=1024, PATCH=16, DOWN=4 -> L=4096 (64x64 patches), M=256.
// att_gt[b,c] = (1/4096) * A_onehot(b,c)[4096x256] @ V(b,c)[256k x 256m]
//   A in {0,1}, V counts in [0,16] -> exact in s8 x s8 -> s32 IMMA.
// Loss = mean over 33,554,432 elements of (att - att_gt)^2.
// target is int32 on disk. tcgen05 is NOT available (ptxas targets compute_103,
// no 'a' feature set) -> use generic mma.sync.m16n8k32.s8 + ldmatrix.

// ---------------- device scratch ----------------
static __device__ __align__(16) uint8_t g_V[8u * 4u * 256u * 256u]; // [b][c][m][k] u8
static __device__ __align__(16) uint8_t g_T[8u * 4096u * 256u];     // [b][l][k] class byte
static __device__ double g_part[512];

// ---------------- kernel 1: pooled counts -> g_V u8 [b][c][m][k] --------
__global__ void k_pool(const int* __restrict__ tgt) {
    __shared__ __align__(16) uint8_t stage[4][16][16];   // [c][m-off][k-off]
    int X = threadIdx.x;
    int Y = blockIdx.x & 255, b = blockIdx.x >> 8;
    const int* p = tgt + ((size_t)b << 20) + (size_t)(Y * 4) * 1024 + X * 4;
    int c0 = 0, c1 = 0, c2 = 0, c3 = 0;
#pragma unroll
    for (int dy = 0; dy < 4; dy++) {
        int4 q = *reinterpret_cast<const int4*>(p + (size_t)dy * 1024);
        c0 += (q.x == 0); c1 += (q.x == 1); c2 += (q.x == 2); c3 += (q.x == 3);
        c0 += (q.y == 0); c1 += (q.y == 1); c2 += (q.y == 2); c3 += (q.y == 3);
        c0 += (q.z == 0); c1 += (q.z == 1); c2 += (q.z == 2); c3 += (q.z == 3);
        c0 += (q.w == 0); c1 += (q.w == 1); c2 += (q.w == 2); c3 += (q.w == 3);
    }
    int mo = X >> 4, ko = X & 15;
    stage[0][mo][ko] = (uint8_t)c0;
    stage[1][mo][ko] = (uint8_t)c1;
    stage[2][mo][ko] = (uint8_t)c2;
    stage[3][mo][ko] = (uint8_t)c3;
    __syncthreads();
    if (X < 64) {
        int c = X >> 4, mo2 = X & 15;
        int mbase = (Y >> 4) << 4, kbase = (Y & 15) << 4;
        uint4 v = *reinterpret_cast<const uint4*>(&stage[c][mo2][0]);
        *reinterpret_cast<uint4*>(g_V + (((size_t)b * 4 + c) << 16)
                                  + (size_t)(mbase + mo2) * 256 + kbase) = v;
    }
}

// ---------------- kernel 2: target -> class bytes g_T[b][l][k] ----------
__global__ void k_compact(const int* __restrict__ tgt) {
    int t = threadIdx.x;
    int py = blockIdx.x & 63, b = blockIdx.x >> 6;
#pragma unroll 4
    for (int ky = 0; ky < 16; ky++) {
        int4 q = *reinterpret_cast<const int4*>(
            tgt + ((size_t)b << 20) + (size_t)(py * 16 + ky) * 1024 + t * 4);
        uint32_t w = (uint32_t)(q.x & 255) | ((uint32_t)(q.y & 255) << 8)
                   | ((uint32_t)(q.z & 255) << 16) | ((uint32_t)(q.w & 255) << 24);
        size_t off = ((size_t)b * 4096 + py * 64 + (t >> 2)) * 256
                   + ky * 16 + (t & 3) * 4;
        *reinterpret_cast<uint32_t*>(g_T + off) = w;
    }
}

// ---------------- kernel 3: IMMA GEMM + fused MSE ------------------------
// grid (mt=64, b=8) = 512 CTAs, 256 threads (8 warps), 2 CTAs/SM.
// SMEM: B s8 [256m][256k] 64KB | A s8 [64l][256k] 16KB | T 16KB | wsum.
// Warp w: l-rows = (w&3)*16..+16, m-half = (w>>2)*128, 2 chunks of 64 m.
static constexpr int SM_B = 0;
static constexpr int SM_A = 65536;
static constexpr int SM_T = 81920;
static constexpr int SM_W = 98304;
static constexpr int SM_TOT = 98304 + 64;

__device__ __forceinline__ uint32_t smem_u32(const void* p) {
    uint32_t a;
    asm("{ .reg .u64 t; cvta.to.shared.u64 t, %1; cvt.u32.u64 %0, t; }"
        : "=r"(a) : "l"(p));
    return a;
}

__global__ void __launch_bounds__(256, 2) k_mma(const float* __restrict__ att) {
    extern __shared__ __align__(16) uint8_t sm[];
    uint32_t smb = smem_u32(sm);
    double* wsum = (double*)(sm + SM_W);
    int tid = threadIdx.x, wid = tid >> 5, lane = tid & 31;
    int mt = blockIdx.x, b = blockIdx.y;

    {   // load T tile: g_T[b][mt*64 .. +64][256] = 16KB contiguous
        const uint4* src = (const uint4*)(g_T + ((size_t)b * 4096 + mt * 64) * 256);
        uint4* dst = (uint4*)(sm + SM_T);
        for (int i = tid; i < 1024; i += 256) dst[i] = src[i];
    }
    __syncthreads();

    const uint32_t* Tw = (const uint32_t*)(sm + SM_T);
    int lgroup = wid & 3, mhalf = wid >> 2;
    int lb = lgroup << 4;
    int gID = lane >> 2, tig = lane & 3;
    const float inv = 1.0f / 4096.0f;
    float s = 0.0f;

    // ldmatrix lane-role constants
    int a_r = lb + (((lane & 15) >= 8) ? 8 : 0) + (lane & 7);
    int a_kadd = (lane >= 16) ? 16 : 0;
    int b_radd = lane & 7;
    int b_kadd = ((lane & 15) >= 8) ? 16 : 0;
    uint32_t a_rowbase = smb + SM_A + a_r * 256;
    uint32_t a_rx = (uint32_t)(a_r & 7) << 4;

    for (int c = 0; c < 4; c++) {
        {   // build A: row r = tid>>2 (64 rows), u32 cols jb..jb+15 (of 64)
            int r = tid >> 2, jb = (tid & 3) << 4;
            uint32_t cc = 0x01010101u * (uint32_t)c;
            uint32_t rb = smb + SM_A + r * 256;
            uint32_t rx = (uint32_t)(r & 7) << 4;
#pragma unroll
            for (int j = 0; j < 16; j++) {
                int jj = jb + j;
                uint32_t eq = __vcmpeq4(Tw[r * 64 + jj], cc) & 0x01010101u;
                uint32_t kb = (uint32_t)jj << 2;
                uint32_t addr = rb + ((kb & 0xF0u) ^ rx) + (kb & 15u);
                asm volatile("st.shared.b32 [%0], %1;" :: "r"(addr), "r"(eq));
            }
        }
        {   // copy B slab: 4096 x 16B, swizzled
            const uint4* src = (const uint4*)(g_V + (((size_t)b * 4 + c) << 16));
#pragma unroll
            for (int i = 0; i < 16; i++) {
                int idx = tid + (i << 8);
                int mr = idx >> 4, ch = idx & 15;
                uint4 v = __ldg(src + idx);
                uint32_t addr = smb + SM_B + mr * 256
                              + ((uint32_t)(ch ^ (mr & 7)) << 4);
                asm volatile("st.shared.v4.b32 [%0], {%1,%2,%3,%4};"
                             :: "r"(addr), "r"(v.x), "r"(v.y), "r"(v.z), "r"(v.w));
            }
        }
        __syncthreads();

#pragma unroll
        for (int chunk = 0; chunk < 2; chunk++) {
            int mb = (mhalf << 7) + (chunk << 6);
            int acc[8][4];
#pragma unroll
            for (int nt = 0; nt < 8; nt++) {
                acc[nt][0] = 0; acc[nt][1] = 0; acc[nt][2] = 0; acc[nt][3] = 0;
            }
#pragma unroll
            for (int ks = 0; ks < 8; ks++) {
                uint32_t akb = (uint32_t)((ks << 5) + a_kadd);
                uint32_t aaddr = a_rowbase + ((akb & 0xF0u) ^ a_rx);
                uint32_t a0, a1, a2, a3;
                asm volatile(
                    "ldmatrix.sync.aligned.m8n8.x4.shared.b16 {%0,%1,%2,%3}, [%4];"
                    : "=r"(a0), "=r"(a1), "=r"(a2), "=r"(a3) : "r"(aaddr));
#pragma unroll
                for (int nt = 0; nt < 8; nt++) {
                    int br = mb + (nt << 3) + b_radd;
                    uint32_t bkb = (uint32_t)((ks << 5) + b_kadd);
                    uint32_t baddr = smb + SM_B + br * 256
                                   + ((uint32_t)(((bkb >> 4) ^ (uint32_t)(br & 7))) << 4);
                    uint32_t b0, b1;
                    asm volatile(
                        "ldmatrix.sync.aligned.m8n8.x2.shared.b16 {%0,%1}, [%2];"
                        : "=r"(b0), "=r"(b1) : "r"(baddr));
                    asm volatile(
                        "mma.sync.aligned.m16n8k32.row.col.s32.s8.s8.s32 "
                        "{%0,%1,%2,%3}, {%4,%5,%6,%7}, {%8,%9}, {%0,%1,%2,%3};"
                        : "+r"(acc[nt][0]), "+r"(acc[nt][1]),
                          "+r"(acc[nt][2]), "+r"(acc[nt][3])
                        : "r"(a0), "r"(a1), "r"(a2), "r"(a3), "r"(b0), "r"(b1));
                }
            }
            // fused MSE epilogue: D rows L=gID, gID+8; cols m = mb+nt*8+tig*2
            int L = (mt << 6) + lb + gID;
            size_t abase = ((((size_t)(b * 4 + c)) * 4096 + L) << 8);
#pragma unroll
            for (int nt = 0; nt < 8; nt++) {
                int m = mb + (nt << 3) + (tig << 1);
                float2 v0 = __ldg((const float2*)(att + abase + m));
                float2 v1 = __ldg((const float2*)(att + abase + 2048 + m));
                float d0 = v0.x - (float)acc[nt][0] * inv;
                float d1 = v0.y - (float)acc[nt][1] * inv;
                float d2 = v1.x - (float)acc[nt][2] * inv;
                float d3 = v1.y - (float)acc[nt][3] * inv;
                s += d0 * d0; s += d1 * d1; s += d2 * d2; s += d3 * d3;
            }
        }
        __syncthreads();   // A/B consumed before next-c overwrite
    }

    // deterministic reduction
#pragma unroll
    for (int o = 16; o > 0; o >>= 1) s += __shfl_down_sync(0xffffffffu, s, o);
    if (lane == 0) wsum[wid] = (double)s;
    __syncthreads();
    if (tid == 0) {
        double t = 0.0;
#pragma unroll
        for (int w = 0; w < 8; w++) t += wsum[w];
        g_part[(size_t)b * 64 + mt] = t;
    }
}

// ---------------- kernel 4: final deterministic reduction ----------------
__global__ void k_final(float* __restrict__ out) {
    __shared__ double sh[256];
    int t = threadIdx.x;
    sh[t] = g_part[t] + g_part[t + 256];
    __syncthreads();
#pragma unroll
    for (int o = 128; o > 0; o >>= 1) {
        if (t < o) sh[t] += sh[t + o];
        __syncthreads();
    }
    if (t == 0) out[0] = (float)(sh[0] / 33554432.0);
}

// ---------------- launch -------------------------------------------------
extern "C" void kernel_launch(void* const* d_in, const int* in_sizes, int n_in,
                              void* d_out, int out_size) {
    (void)in_sizes; (void)n_in; (void)out_size;
    // d_in[0] = pred (unused), d_in[1] = target int32, d_in[2] = attentions f32
    const int*   tgt = (const int*)d_in[1];
    const float* att = (const float*)d_in[2];
    float*       out = (float*)d_out;

    cudaFuncSetAttribute(k_mma, cudaFuncAttributeMaxDynamicSharedMemorySize,
                         SM_TOT);

    k_pool<<<2048, 256>>>(tgt);
    k_compact<<<512, 256>>>(tgt);
    k_mma<<<dim3(64, 8), 256, SM_TOT>>>(att);
    k_final<<<1, 256>>>(out);
}

// round 12
// speedup vs baseline: 1.1026x; 1.1026x over previous
#include <cuda_runtime.h>
#include <cstdint>

// B=8, C=4, H=W=1024, PATCH=16, DOWN=4 -> L=4096 (64x64 patches), M=256.
// att_gt[b,c] = (1/4096) * A_onehot(b,c)[4096x256] @ V(b,c)[256k x 256m]
//   A in {0,1}, V counts in [0,16] -> exact in s8 x s8 -> s32 IMMA.
// Loss = mean over 33,554,432 elements of (att - att_gt)^2.
// target is int32 on disk. tcgen05 unavailable (ptxas targets compute_103) ->
// generic mma.sync.m16n8k32.s8 + ldmatrix, tuned for occupancy/latency.

// ---------------- device scratch ----------------
static __device__ __align__(16) uint8_t g_V[8u * 4u * 256u * 256u]; // [b][c][m][k] u8
static __device__ __align__(16) uint8_t g_T[8u * 4096u * 256u];     // [b][l][k] class byte
static __device__ double g_part[1024];

// ---------------- kernel 1: pooled counts -> g_V u8 [b][c][m][k] --------
__global__ void k_pool(const int* __restrict__ tgt) {
    __shared__ __align__(16) uint8_t stage[4][16][16];   // [c][m-off][k-off]
    int X = threadIdx.x;
    int Y = blockIdx.x & 255, b = blockIdx.x >> 8;
    const int* p = tgt + ((size_t)b << 20) + (size_t)(Y * 4) * 1024 + X * 4;
    int c0 = 0, c1 = 0, c2 = 0, c3 = 0;
#pragma unroll
    for (int dy = 0; dy < 4; dy++) {
        int4 q = *reinterpret_cast<const int4*>(p + (size_t)dy * 1024);
        c0 += (q.x == 0); c1 += (q.x == 1); c2 += (q.x == 2); c3 += (q.x == 3);
        c0 += (q.y == 0); c1 += (q.y == 1); c2 += (q.y == 2); c3 += (q.y == 3);
        c0 += (q.z == 0); c1 += (q.z == 1); c2 += (q.z == 2); c3 += (q.z == 3);
        c0 += (q.w == 0); c1 += (q.w == 1); c2 += (q.w == 2); c3 += (q.w == 3);
    }
    int mo = X >> 4, ko = X & 15;
    stage[0][mo][ko] = (uint8_t)c0;
    stage[1][mo][ko] = (uint8_t)c1;
    stage[2][mo][ko] = (uint8_t)c2;
    stage[3][mo][ko] = (uint8_t)c3;
    __syncthreads();
    if (X < 64) {
        int c = X >> 4, mo2 = X & 15;
        int mbase = (Y >> 4) << 4, kbase = (Y & 15) << 4;
        uint4 v = *reinterpret_cast<const uint4*>(&stage[c][mo2][0]);
        *reinterpret_cast<uint4*>(g_V + (((size_t)b * 4 + c) << 16)
                                  + (size_t)(mbase + mo2) * 256 + kbase) = v;
    }
}

// ---------------- kernel 2: target -> class bytes g_T[b][l][k] ----------
__global__ void k_compact(const int* __restrict__ tgt) {
    int t = threadIdx.x;
    int py = blockIdx.x & 63, b = blockIdx.x >> 6;
#pragma unroll 4
    for (int ky = 0; ky < 16; ky++) {
        int4 q = *reinterpret_cast<const int4*>(
            tgt + ((size_t)b << 20) + (size_t)(py * 16 + ky) * 1024 + t * 4);
        uint32_t w = (uint32_t)(q.x & 255) | ((uint32_t)(q.y & 255) << 8)
                   | ((uint32_t)(q.z & 255) << 16) | ((uint32_t)(q.w & 255) << 24);
        size_t off = ((size_t)b * 4096 + py * 64 + (t >> 2)) * 256
                   + ky * 16 + (t & 3) * 4;
        *reinterpret_cast<uint32_t*>(g_T + off) = w;
    }
}

// ---------------- kernel 3: IMMA GEMM + fused MSE ------------------------
// grid (lt=64, mh=2, b=8) = 1024 CTAs, 256 threads (8 warps), occ 3.
// SMEM: B s8 [128m][256k] 32KB | A s8 [64l][256k] 16KB | T 16KB | wsum.
// Warp w: l-rows (w&3)*16..+16, m-offset (w>>2)*64 within the CTA's 128.
static constexpr int SM_B = 0;
static constexpr int SM_A = 32768;
static constexpr int SM_T = 49152;
static constexpr int SM_W = 65536;
static constexpr int SM_TOT = 65536 + 64;

__device__ __forceinline__ uint32_t smem_u32(const void* p) {
    uint32_t a;
    asm("{ .reg .u64 t; cvta.to.shared.u64 t, %1; cvt.u32.u64 %0, t; }"
        : "=r"(a) : "l"(p));
    return a;
}

__global__ void __launch_bounds__(256, 3) k_mma(const float* __restrict__ att) {
    extern __shared__ __align__(16) uint8_t sm[];
    uint32_t smb = smem_u32(sm);
    double* wsum = (double*)(sm + SM_W);
    int tid = threadIdx.x, wid = tid >> 5, lane = tid & 31;
    int lt = blockIdx.x, mh = blockIdx.y, b = blockIdx.z;

    {   // load T tile: g_T[b][lt*64 .. +64][256] = 16KB contiguous
        const uint4* src = (const uint4*)(g_T + ((size_t)b * 4096 + lt * 64) * 256);
        uint4* dst = (uint4*)(sm + SM_T);
        for (int i = tid; i < 1024; i += 256) dst[i] = src[i];
    }
    __syncthreads();

    const uint32_t* Tw = (const uint32_t*)(sm + SM_T);
    int lb = (wid & 3) << 4;          // warp's l-row base (16 rows)
    int mb = (wid >> 2) << 6;         // warp's m base within 128 (64 cols)
    int gID = lane >> 2, tig = lane & 3;
    const float inv = 1.0f / 4096.0f;
    float s = 0.0f;

    // ldmatrix lane-role constants
    int a_r = lb + (((lane & 15) >= 8) ? 8 : 0) + (lane & 7);
    uint32_t a_kadd = (lane >= 16) ? 16u : 0u;
    uint32_t a_rx = (uint32_t)(a_r & 7) << 4;
    uint32_t a_rowbase = smb + SM_A + a_r * 256;
    uint32_t b_kadd1 = ((lane & 15) >= 8) ? 1u : 0u;  // in 16B units
    uint32_t b_rowbase = smb + SM_B + (uint32_t)(mb + (lane & 7)) * 256;
    uint32_t b_lx = (uint32_t)(lane & 7);

    for (int c = 0; c < 4; c++) {
        {   // build A: row r = tid>>2 (64 rows), u32 cols jb..jb+15 (of 64)
            int r = tid >> 2, jb = (tid & 3) << 4;
            uint32_t cc = 0x01010101u * (uint32_t)c;
            uint32_t rb = smb + SM_A + r * 256;
            uint32_t rx = (uint32_t)(r & 7) << 4;
#pragma unroll
            for (int j = 0; j < 16; j++) {
                int jj = jb + j;
                uint32_t eq = __vcmpeq4(Tw[r * 64 + jj], cc) & 0x01010101u;
                uint32_t kb = (uint32_t)jj << 2;
                uint32_t addr = rb + ((kb & 0xF0u) ^ rx) + (kb & 15u);
                asm volatile("st.shared.b32 [%0], %1;" :: "r"(addr), "r"(eq));
            }
        }
        {   // copy B slab: m rows [mh*128, +128) -> 2048 x 16B, swizzled
            const uint4* src = (const uint4*)(g_V + (((size_t)b * 4 + c) << 16)
                                              + ((size_t)mh << 15));
#pragma unroll
            for (int i = 0; i < 8; i++) {
                int idx = tid + (i << 8);
                int mr = idx >> 4, ch = idx & 15;
                uint4 v = __ldg(src + idx);
                uint32_t addr = smb + SM_B + mr * 256
                              + ((uint32_t)(ch ^ (mr & 7)) << 4);
                asm volatile("st.shared.v4.b32 [%0], {%1,%2,%3,%4};"
                             :: "r"(addr), "r"(v.x), "r"(v.y), "r"(v.z), "r"(v.w));
            }
        }
        __syncthreads();

        int acc[8][4];
#pragma unroll
        for (int nt = 0; nt < 8; nt++) {
            acc[nt][0] = 0; acc[nt][1] = 0; acc[nt][2] = 0; acc[nt][3] = 0;
        }
#pragma unroll
        for (int ks = 0; ks < 8; ks++) {
            uint32_t akb = (uint32_t)(ks << 5) + a_kadd;
            uint32_t aaddr = a_rowbase + (akb ^ a_rx);
            uint32_t a0, a1, a2, a3;
            asm volatile(
                "ldmatrix.sync.aligned.m8n8.x4.shared.b16 {%0,%1,%2,%3}, [%4];"
                : "=r"(a0), "=r"(a1), "=r"(a2), "=r"(a3) : "r"(aaddr));
            // batch all 8 independent B fragment loads
            uint32_t bxor = (((uint32_t)(ks << 1) + b_kadd1) ^ b_lx) << 4;
            uint32_t bf0[8], bf1[8];
#pragma unroll
            for (int nt = 0; nt < 8; nt++) {
                uint32_t baddr = b_rowbase + (uint32_t)(nt << 11) + bxor;
                asm volatile(
                    "ldmatrix.sync.aligned.m8n8.x2.shared.b16 {%0,%1}, [%2];"
                    : "=r"(bf0[nt]), "=r"(bf1[nt]) : "r"(baddr));
            }
#pragma unroll
            for (int nt = 0; nt < 8; nt++) {
                asm volatile(
                    "mma.sync.aligned.m16n8k32.row.col.s32.s8.s8.s32 "
                    "{%0,%1,%2,%3}, {%4,%5,%6,%7}, {%8,%9}, {%0,%1,%2,%3};"
                    : "+r"(acc[nt][0]), "+r"(acc[nt][1]),
                      "+r"(acc[nt][2]), "+r"(acc[nt][3])
                    : "r"(a0), "r"(a1), "r"(a2), "r"(a3),
                      "r"(bf0[nt]), "r"(bf1[nt]));
            }
        }

        // fused MSE epilogue: D rows L=..gID / +8; cols m = mh*128+mb+nt*8+tig*2
        int L = (lt << 6) + lb + gID;
        size_t abase = ((((size_t)(b * 4 + c)) * 4096 + L) << 8);
#pragma unroll
        for (int nt = 0; nt < 8; nt++) {
            int m = (mh << 7) + mb + (nt << 3) + (tig << 1);
            float2 v0 = __ldg((const float2*)(att + abase + m));
            float2 v1 = __ldg((const float2*)(att + abase + 2048 + m));
            float d0 = v0.x - (float)acc[nt][0] * inv;
            float d1 = v0.y - (float)acc[nt][1] * inv;
            float d2 = v1.x - (float)acc[nt][2] * inv;
            float d3 = v1.y - (float)acc[nt][3] * inv;
            s += d0 * d0; s += d1 * d1; s += d2 * d2; s += d3 * d3;
        }
        __syncthreads();   // A/B consumed before next-c overwrite
    }

    // deterministic reduction
#pragma unroll
    for (int o = 16; o > 0; o >>= 1) s += __shfl_down_sync(0xffffffffu, s, o);
    if (lane == 0) wsum[wid] = (double)s;
    __syncthreads();
    if (tid == 0) {
        double t = 0.0;
#pragma unroll
        for (int w = 0; w < 8; w++) t += wsum[w];
        g_part[((size_t)b * 2 + mh) * 64 + lt] = t;
    }
}

// ---------------- kernel 4: final deterministic reduction ----------------
__global__ void k_final(float* __restrict__ out) {
    __shared__ double sh[256];
    int t = threadIdx.x;
    sh[t] = g_part[t] + g_part[t + 256] + g_part[t + 512] + g_part[t + 768];
    __syncthreads();
#pragma unroll
    for (int o = 128; o > 0; o >>= 1) {
        if (t < o) sh[t] += sh[t + o];
        __syncthreads();
    }
    if (t == 0) out[0] = (float)(sh[0] / 33554432.0);
}

// ---------------- launch -------------------------------------------------
extern "C" void kernel_launch(void* const* d_in, const int* in_sizes, int n_in,
                              void* d_out, int out_size) {
    (void)in_sizes; (void)n_in; (void)out_size;
    // d_in[0] = pred (unused), d_in[1] = target int32, d_in[2] = attentions f32
    const int*   tgt = (const int*)d_in[1];
    const float* att = (const float*)d_in[2];
    float*       out = (float*)d_out;

    cudaFuncSetAttribute(k_mma, cudaFuncAttributeMaxDynamicSharedMemorySize,
                         SM_TOT);

    k_pool<<<2048, 256>>>(tgt);
    k_compact<<<512, 256>>>(tgt);
    k_mma<<<dim3(64, 2, 8), 256, SM_TOT>>>(att);
    k_final<<<1, 256>>>(out);
}